// round 1
// baseline (speedup 1.0000x reference)
#include <cuda_runtime.h>

// Problem constants (fixed shapes from the reference)
#define B_   16
#define T_   1024
#define BT_  16384      // B*T
#define R_   16
#define NP_  64
#define NC_  32
#define NL_  20
#define H_   256
#define N_   1024       // R*NP
#define RC_  512        // R*NC
#define RL_  320        // R*NL

// Scratch (no allocation allowed -> device globals)
__device__ float g_emb[BT_ * RC_];   // (BT, 512)
__device__ float g_h  [BT_ * H_ ];   // (BT, 256)
__device__ float g_lat[BT_ * RL_];   // (BT, 320)
__device__ double g_loss_acc;
__device__ double g_reg_acc;

__global__ void zero_acc_kernel() {
    g_loss_acc = 0.0;
    g_reg_acc  = 0.0;
}

// ---------------------------------------------------------------------------
// Generic tiled SGEMM:  C[z] = (A[z] @ B[z] + bias[z]) * scale(z)
// A row-major [M x K] (lda), B row-major [K x N] (ldb), C row-major (ldc).
// blockIdx.z selects the "area" slice via byte-free element strides sAz/sBz/...
// If LOSS: also accumulate sum(exp(c) - tgt*c) into g_loss_acc.
// ---------------------------------------------------------------------------
template<int BM, int BN, int BK, int TM, int TN, bool LOSS>
__global__ void __launch_bounds__((BM/TM)*(BN/TN))
sgemm_k(const float* __restrict__ A, int lda, long long sAz,
        const float* __restrict__ Bmat, int ldb, long long sBz,
        const float* __restrict__ bias, int sbz,
        float* __restrict__ C, int ldc, long long sCz,
        int N, int K,
        const int* __restrict__ mask,
        const float* __restrict__ tgt, int ldt, long long sTz)
{
    constexpr int NT = (BM/TM)*(BN/TN);
    __shared__ float As[BK][BM + 1];
    __shared__ float Bs[BK][BN];

    const int z = blockIdx.z;
    A    += (long long)z * sAz;
    Bmat += (long long)z * sBz;
    C    += (long long)z * sCz;
    if (bias) bias += (long long)z * sbz;
    if (LOSS) tgt  += (long long)z * sTz;
    const float scale = mask ? (float)mask[z] : 1.0f;

    const int m0  = blockIdx.x * BM;
    const int n0  = blockIdx.y * BN;
    const int tid = threadIdx.x;
    const int tc  = tid % (BN / TN);
    const int tr  = tid / (BN / TN);

    float acc[TM][TN];
    #pragma unroll
    for (int i = 0; i < TM; i++)
        #pragma unroll
        for (int j = 0; j < TN; j++) acc[i][j] = 0.f;

    for (int k0 = 0; k0 < K; k0 += BK) {
        // Load A tile (BM x BK), store transposed As[k][m]
        #pragma unroll
        for (int i = tid; i < BM * BK; i += NT) {
            int m  = i / BK;
            int kk = i % BK;
            As[kk][m] = (k0 + kk < K)
                ? A[(long long)(m0 + m) * lda + (k0 + kk)] : 0.f;
        }
        // Load B tile (BK x BN)
        #pragma unroll
        for (int i = tid; i < BK * BN; i += NT) {
            int kk = i / BN;
            int n  = i % BN;
            Bs[kk][n] = (k0 + kk < K)
                ? Bmat[(long long)(k0 + kk) * ldb + (n0 + n)] : 0.f;
        }
        __syncthreads();

        #pragma unroll
        for (int kk = 0; kk < BK; kk++) {
            float ra[TM], rb[TN];
            #pragma unroll
            for (int i = 0; i < TM; i++) ra[i] = As[kk][tr * TM + i];
            #pragma unroll
            for (int j = 0; j < TN; j++) rb[j] = Bs[kk][tc * TN + j];
            #pragma unroll
            for (int i = 0; i < TM; i++)
                #pragma unroll
                for (int j = 0; j < TN; j++)
                    acc[i][j] = fmaf(ra[i], rb[j], acc[i][j]);
        }
        __syncthreads();
    }

    float lsum = 0.f;
    #pragma unroll
    for (int i = 0; i < TM; i++) {
        const int m = m0 + tr * TM + i;
        #pragma unroll
        for (int j = 0; j < TN; j++) {
            const int n = n0 + tc * TN + j;
            float v = acc[i][j];
            if (bias) v += bias[n];
            v *= scale;
            C[(long long)m * ldc + n] = v;
            if (LOSS) {
                float t = tgt[(long long)m * ldt + n];
                lsum += __expf(v) - t * v;
            }
        }
    }

    if (LOSS) {
        __shared__ float red[NT];
        red[tid] = lsum;
        __syncthreads();
        #pragma unroll
        for (int s = NT / 2; s > 0; s >>= 1) {
            if (tid < s) red[tid] += red[tid + s];
            __syncthreads();
        }
        if (tid == 0) atomicAdd(&g_loss_acc, (double)red[0]);
    }
}

// reg_loss = mean(|lat[b,t+1,:] - lat[b,t,:]|) over (B, T-1, RL)
__global__ void reg_kernel() {
    const long long total = (long long)B_ * (T_ - 1) * RL_;
    float local = 0.f;
    for (long long idx = blockIdx.x * (long long)blockDim.x + threadIdx.x;
         idx < total;
         idx += (long long)gridDim.x * blockDim.x) {
        int c = (int)(idx % RL_);
        long long bt = idx / RL_;
        int t = (int)(bt % (T_ - 1));
        int b = (int)(bt / (T_ - 1));
        long long base = ((long long)b * T_ + t) * RL_ + c;
        local += fabsf(g_lat[base + RL_] - g_lat[base]);
    }
    __shared__ float red[256];
    red[threadIdx.x] = local;
    __syncthreads();
    #pragma unroll
    for (int s = 128; s > 0; s >>= 1) {
        if (threadIdx.x < s) red[threadIdx.x] += red[threadIdx.x + s];
        __syncthreads();
    }
    if (threadIdx.x == 0) atomicAdd(&g_reg_acc, (double)red[0]);
}

__global__ void finalize_kernel(float* __restrict__ out) {
    out[0] = (float)(g_loss_acc / ((double)BT_ * (double)N_));
    out[1] = (float)(g_reg_acc * 0.1 / ((double)B_ * (double)(T_ - 1) * (double)RL_));
}

extern "C" void kernel_launch(void* const* d_in, const int* in_sizes, int n_in,
                              void* d_out, int out_size) {
    const float* spikes = (const float*)d_in[0];
    // d_in[1] = neuron_regions (contiguous areas by construction; unused)
    const int*   keep_mask = (const int*)d_in[2];
    const float* W_st  = (const float*)d_in[3];
    const float* b_st  = (const float*)d_in[4];
    const float* W_U   = (const float*)d_in[5];
    const float* b_U   = (const float*)d_in[6];
    const float* W_V   = (const float*)d_in[7];
    const float* b_V   = (const float*)d_in[8];
    const float* W_dec = (const float*)d_in[9];
    const float* b_dec = (const float*)d_in[10];

    float* out   = (float*)d_out;
    float* preds = out + 2;

    float* emb; float* h; float* lat;
    cudaGetSymbolAddress((void**)&emb, g_emb);
    cudaGetSymbolAddress((void**)&h,   g_h);
    cudaGetSymbolAddress((void**)&lat, g_lat);

    zero_acc_kernel<<<1, 1>>>();

    // K1: stitch per area + bias + mask -> emb (BT, 512)
    // per z: A = spikes[:, z*64:(z+1)*64], B = W_st[z] (64x32), C = emb[:, z*32:...]
    sgemm_k<128, 32, 16, 8, 4, false><<<dim3(BT_/128, 1, R_), 128>>>(
        spikes, N_, NP_,
        W_st, NC_, (long long)NP_ * NC_,
        b_st, NC_,
        emb, RC_, NC_,
        /*N=*/NC_, /*K=*/NP_,
        keep_mask, nullptr, 0, 0);

    // K2: h = emb @ W_U + b_U   (16384 x 256, K=512)
    sgemm_k<128, 64, 16, 8, 4, false><<<dim3(BT_/128, H_/64, 1), 256>>>(
        emb, RC_, 0,
        W_U, H_, 0,
        b_U, 0,
        h, H_, 0,
        /*N=*/H_, /*K=*/RC_,
        nullptr, nullptr, 0, 0);

    // K3: lat = h @ W_V + b_V   (16384 x 320, K=256)
    sgemm_k<128, 64, 16, 8, 4, false><<<dim3(BT_/128, RL_/64, 1), 256>>>(
        h, H_, 0,
        W_V, RL_, 0,
        b_V, 0,
        lat, RL_, 0,
        /*N=*/RL_, /*K=*/H_,
        nullptr, nullptr, 0, 0);

    // K4: decoder per area + bias -> preds, fused Poisson-NLL accumulation
    // per z: A = lat[:, z*20:...], B = W_dec[z] (20x64), C = preds[:, z*64:...]
    sgemm_k<128, 64, 16, 8, 4, true><<<dim3(BT_/128, 1, R_), 256>>>(
        lat, RL_, NL_,
        W_dec, NP_, (long long)NL_ * NP_,
        b_dec, NP_,
        preds, N_, NP_,
        /*N=*/NP_, /*K=*/NL_,
        nullptr, spikes, N_, NP_);

    // K5: reg loss over lat diffs
    reg_kernel<<<1024, 256>>>();

    // K6: scalars
    finalize_kernel<<<1, 1>>>(out);
}

// round 3
// speedup vs baseline: 1.5717x; 1.5717x over previous
#include <cuda_runtime.h>
#include <cstdint>

// Problem constants (fixed shapes)
#define B_   16
#define T_   1024
#define BT_  16384      // B*T
#define R_   16
#define NP_  64
#define NC_  32
#define NL_  20
#define H_   256
#define N_   1024       // R*NP
#define RC_  512        // R*NC
#define RL_  320        // R*NL

// tcgen05 is arch-SPECIFIC (sm_103a / sm_100a). The harness also runs a
// family-generic compute_103 ptxas pass where these instructions are illegal,
// so gate the tensor-core body on the feature macros.
#if defined(__CUDA_ARCH_FEAT_SM103_ALL) || defined(__CUDA_ARCH_FEAT_SM100_ALL)
#define TC_OK 1
#else
#define TC_OK 0
#endif

// Scratch (no allocation allowed -> device globals)
__device__ float g_emb[BT_ * RC_];   // (BT, 512)
__device__ float g_h  [BT_ * H_ ];   // (BT, 256)
__device__ float g_lat[BT_ * RL_];   // (BT, 320)
__device__ float g_WUt[H_ * RC_];    // W_U^T : (256, 512) row-major = [N,K]
__device__ float g_WVt[RL_ * H_];    // W_V^T : (320, 256) row-major = [N,K]
__device__ double g_loss_acc;
__device__ double g_reg_acc;

__global__ void zero_acc_kernel() {
    g_loss_acc = 0.0;
    g_reg_acc  = 0.0;
}

// Transpose [K,N] -> [N,K]
__global__ void transpose_k(const float* __restrict__ in, float* __restrict__ out,
                            int K, int N) {
    int idx = blockIdx.x * blockDim.x + threadIdx.x;
    if (idx < K * N) {
        int k = idx / N, n = idx % N;
        out[n * K + k] = in[idx];
    }
}

// ---------------------------------------------------------------------------
// PTX helpers (tcgen05 ones only compiled in the arch-specific pass)
// ---------------------------------------------------------------------------
__device__ __forceinline__ uint32_t smem_u32(const void* p) {
    uint32_t a;
    asm("{ .reg .u64 t; cvta.to.shared.u64 t, %1; cvt.u32.u64 %0, t; }"
        : "=r"(a) : "l"(p));
    return a;
}
__device__ __forceinline__ uint32_t tf32r(float x) {
    uint32_t u;
    asm("cvt.rna.tf32.f32 %0, %1;" : "=r"(u) : "f"(x));
    return u;
}

#if TC_OK
__device__ __forceinline__ bool elect_one() {
    uint32_t pred;
    asm volatile("{\n\t.reg .pred p;\n\telect.sync _|p, 0xFFFFFFFF;\n\t"
                 "selp.b32 %0, 1, 0, p;\n\t}" : "=r"(pred));
    return pred != 0;
}
__device__ __forceinline__ void mbar_init(uint32_t mbar, uint32_t cnt) {
    asm volatile("mbarrier.init.shared.b64 [%0], %1;" :: "r"(mbar), "r"(cnt) : "memory");
}
__device__ __forceinline__ void mbar_wait(uint32_t mbar, uint32_t parity) {
    asm volatile(
        "{\n\t.reg .pred P;\n\t"
        "WAIT_%=:\n\t"
        "mbarrier.try_wait.parity.acquire.cta.shared::cta.b64 P, [%0], %1, 0x989680;\n\t"
        "@!P bra WAIT_%=;\n\t}"
        :: "r"(mbar), "r"(parity) : "memory");
}
__device__ __forceinline__ void tmem_alloc(uint32_t dst_smem, uint32_t ncols) {
    asm volatile("tcgen05.alloc.cta_group::1.sync.aligned.shared::cta.b32 [%0], %1;"
                 :: "r"(dst_smem), "r"(ncols) : "memory");
}
__device__ __forceinline__ void tmem_dealloc(uint32_t tmem, uint32_t ncols) {
    asm volatile("tcgen05.relinquish_alloc_permit.cta_group::1.sync.aligned;");
    asm volatile("tcgen05.dealloc.cta_group::1.sync.aligned.b32 %0, %1;"
                 :: "r"(tmem), "r"(ncols));
}
__device__ __forceinline__ void tc_commit(uint32_t mbar) {
    asm volatile("tcgen05.commit.cta_group::1.mbarrier::arrive::one.shared::cluster.b64 [%0];"
                 :: "r"(mbar) : "memory");
}
__device__ __forceinline__ void mma_tf32_ss(uint32_t d_tmem, uint64_t a_desc,
                                            uint64_t b_desc, uint32_t idesc,
                                            uint32_t enable_d) {
    asm volatile(
        "{\n\t.reg .pred p;\n\t"
        "setp.ne.u32 p, %5, 0;\n\t"
        "tcgen05.mma.cta_group::1.kind::tf32 [%0], %1, %2, %3, {%4, %4, %4, %4}, p;\n\t"
        "}"
        :: "r"(d_tmem), "l"(a_desc), "l"(b_desc), "r"(idesc), "r"(0u), "r"(enable_d)
        : "memory");
}
#define TC_LD_X32(r, addr) \
    asm volatile( \
        "tcgen05.ld.sync.aligned.32x32b.x32.b32 " \
        "{%0, %1, %2, %3, %4, %5, %6, %7, " \
        " %8, %9, %10, %11, %12, %13, %14, %15, " \
        " %16, %17, %18, %19, %20, %21, %22, %23, " \
        " %24, %25, %26, %27, %28, %29, %30, %31}, [%32];" \
        : "=r"((r)[0]),  "=r"((r)[1]),  "=r"((r)[2]),  "=r"((r)[3]), \
          "=r"((r)[4]),  "=r"((r)[5]),  "=r"((r)[6]),  "=r"((r)[7]), \
          "=r"((r)[8]),  "=r"((r)[9]),  "=r"((r)[10]), "=r"((r)[11]), \
          "=r"((r)[12]), "=r"((r)[13]), "=r"((r)[14]), "=r"((r)[15]), \
          "=r"((r)[16]), "=r"((r)[17]), "=r"((r)[18]), "=r"((r)[19]), \
          "=r"((r)[20]), "=r"((r)[21]), "=r"((r)[22]), "=r"((r)[23]), \
          "=r"((r)[24]), "=r"((r)[25]), "=r"((r)[26]), "=r"((r)[27]), \
          "=r"((r)[28]), "=r"((r)[29]), "=r"((r)[30]), "=r"((r)[31]) \
        : "r"(addr))
#endif  // TC_OK

static constexpr uint64_t DESC_BASE_SW128 =
    (uint64_t(2)  << 61) | (uint64_t(1) << 46) | (uint64_t(64) << 32) | (uint64_t(1) << 16);
__device__ __forceinline__ uint64_t make_desc(uint32_t addr) {
    return DESC_BASE_SW128 | ((uint64_t)(addr >> 4) & 0x3FFF);
}

// ---------------------------------------------------------------------------
// tcgen05 tf32 GEMM: C[m0:m0+128, n0:n0+N_TILE] = A @ Bt^T + bias
// A: row-major [BT, lda]; Bt: row-major [N, K_TOTAL] (pre-transposed weights).
// Blocked SW128 atom layout (K-major), KC=64-float chunks, D accumulated in TMEM.
// ---------------------------------------------------------------------------
template<int N_TILE, int K_TOTAL>
__global__ void __launch_bounds__(128)
tc_gemm_k(const float* __restrict__ A, int lda,
          const float* __restrict__ Bt,
          const float* __restrict__ bias,
          float* __restrict__ C, int ldc)
{
#if TC_OK
    constexpr int KC = 64;                       // floats of K per chunk
    constexpr int A_BYTES = 128 * 256;           // 128 rows x 256B
    constexpr uint32_t A_COLSTRIDE_B = 16u * 1024u;             // 16 atom-rows
    constexpr uint32_t B_COLSTRIDE_B = (uint32_t)(N_TILE / 8) * 1024u;
    constexpr uint32_t IDESC = (1u << 4)         // c_format = F32
                             | (2u << 7)         // a_format = TF32
                             | (2u << 10)        // b_format = TF32
                             | ((uint32_t)(N_TILE / 8) << 17)
                             | (8u << 24);       // M = 128

    extern __shared__ char smem[];
    const uint32_t sbase  = smem_u32(smem);
    const uint32_t ctrl   = sbase;                                // +0 tmem ptr, +8 mbar
    const uint32_t a_base = (sbase + 16u + 1023u) & ~1023u;
    const uint32_t b_base = a_base + A_BYTES;

    const int tid  = threadIdx.x;
    const int wid  = tid >> 5;
    const int lane = tid & 31;
    const int m0   = blockIdx.x * 128;
    const int n0   = blockIdx.y * N_TILE;

    if (wid == 0) tmem_alloc(ctrl, 256);
    if (tid == 0) mbar_init(ctrl + 8, 1);
    __syncthreads();
    uint32_t tmem;
    asm volatile("ld.shared.b32 %0, [%1];" : "=r"(tmem) : "r"(ctrl));

    uint32_t phase = 0;
    for (int k0 = 0; k0 < K_TOTAL; k0 += KC) {
        // ---- A tile: 128 rows x 64 floats (16 float4 per row) ----
        #pragma unroll
        for (int it = 0; it < 16; it++) {
            int i = it * 128 + tid;
            int r = i >> 4;
            int c = (i & 15) * 4;
            float4 v = *reinterpret_cast<const float4*>(
                &A[(size_t)(m0 + r) * lda + k0 + c]);
            uint32_t x = tf32r(v.x), y = tf32r(v.y), z = tf32r(v.z), w = tf32r(v.w);
            uint32_t byte = (uint32_t)(r >> 3) * 1024u
                          + (uint32_t)(c >> 5) * A_COLSTRIDE_B
                          + (uint32_t)(r & 7) * 128u
                          + (uint32_t)(c & 31) * 4u;
            byte ^= (byte >> 3) & 0x70u;
            asm volatile("st.shared.v4.b32 [%0], {%1,%2,%3,%4};"
                         :: "r"(a_base + byte), "r"(x), "r"(y), "r"(z), "r"(w));
        }
        // ---- B tile: N_TILE rows x 64 floats ----
        #pragma unroll
        for (int it = 0; it < N_TILE / 8; it++) {
            int i = it * 128 + tid;
            int r = i >> 4;
            int c = (i & 15) * 4;
            float4 v = *reinterpret_cast<const float4*>(
                &Bt[(size_t)(n0 + r) * K_TOTAL + k0 + c]);
            uint32_t x = tf32r(v.x), y = tf32r(v.y), z = tf32r(v.z), w = tf32r(v.w);
            uint32_t byte = (uint32_t)(r >> 3) * 1024u
                          + (uint32_t)(c >> 5) * B_COLSTRIDE_B
                          + (uint32_t)(r & 7) * 128u
                          + (uint32_t)(c & 31) * 4u;
            byte ^= (byte >> 3) & 0x70u;
            asm volatile("st.shared.v4.b32 [%0], {%1,%2,%3,%4};"
                         :: "r"(b_base + byte), "r"(x), "r"(y), "r"(z), "r"(w));
        }
        __syncthreads();

        if (wid == 0) {
            asm volatile("fence.proxy.async.shared::cta;" ::: "memory");
            if (elect_one()) {
                uint64_t ad = make_desc(a_base);
                uint64_t bd = make_desc(b_base);
                #pragma unroll
                for (int s = 0; s < 8; s++) {    // 8 x K=8 tf32 steps = KC
                    uint64_t aoff = (uint64_t)((s >> 2) * (A_COLSTRIDE_B >> 4) + (s & 3) * 2);
                    uint64_t boff = (uint64_t)((s >> 2) * (B_COLSTRIDE_B >> 4) + (s & 3) * 2);
                    uint32_t en = (k0 > 0 || s > 0) ? 1u : 0u;
                    mma_tf32_ss(tmem, ad + aoff, bd + boff, IDESC, en);
                }
                tc_commit(ctrl + 8);
            }
        }
        mbar_wait(ctrl + 8, phase);
        phase ^= 1;
    }

    asm volatile("tcgen05.fence::after_thread_sync;" ::: "memory");

    // Epilogue: each warp reads its 32-lane TMEM subpartition
    const int m = m0 + wid * 32 + lane;
    #pragma unroll
    for (int nb = 0; nb < N_TILE; nb += 32) {
        uint32_t d[32];
        TC_LD_X32(d, tmem + nb);
        asm volatile("tcgen05.wait::ld.sync.aligned;" ::: "memory");
        #pragma unroll
        for (int j = 0; j < 32; j += 4) {
            float4 o;
            o.x = __uint_as_float(d[j + 0]) + bias[n0 + nb + j + 0];
            o.y = __uint_as_float(d[j + 1]) + bias[n0 + nb + j + 1];
            o.z = __uint_as_float(d[j + 2]) + bias[n0 + nb + j + 2];
            o.w = __uint_as_float(d[j + 3]) + bias[n0 + nb + j + 3];
            *reinterpret_cast<float4*>(&C[(size_t)m * ldc + n0 + nb + j]) = o;
        }
    }
    asm volatile("tcgen05.fence::before_thread_sync;" ::: "memory");
    __syncthreads();
    if (tid == 0)
        asm volatile("mbarrier.inval.shared.b64 [%0];" :: "r"(ctrl + 8) : "memory");
    __syncthreads();
    if (wid == 0) tmem_dealloc(tmem, 256);
#endif  // TC_OK
}

// ---------------------------------------------------------------------------
// Scalar tiled SGEMM for the block-diagonal stages (K1 stitch, K4 decode+loss)
// ---------------------------------------------------------------------------
template<int BM, int BN, int BK, int TM, int TN, bool LOSS>
__global__ void __launch_bounds__((BM/TM)*(BN/TN))
sgemm_k(const float* __restrict__ A, int lda, long long sAz,
        const float* __restrict__ Bmat, int ldb, long long sBz,
        const float* __restrict__ bias, int sbz,
        float* __restrict__ C, int ldc, long long sCz,
        int N, int K,
        const int* __restrict__ mask,
        const float* __restrict__ tgt, int ldt, long long sTz)
{
    constexpr int NT = (BM/TM)*(BN/TN);
    __shared__ float As[BK][BM + 1];
    __shared__ float Bs[BK][BN];

    const int z = blockIdx.z;
    A    += (long long)z * sAz;
    Bmat += (long long)z * sBz;
    C    += (long long)z * sCz;
    if (bias) bias += (long long)z * sbz;
    if (LOSS) tgt  += (long long)z * sTz;
    const float scale = mask ? (float)mask[z] : 1.0f;

    const int m0  = blockIdx.x * BM;
    const int n0  = blockIdx.y * BN;
    const int tid = threadIdx.x;
    const int tc  = tid % (BN / TN);
    const int tr  = tid / (BN / TN);

    // Masked-region fast path: output is identically zero
    if (!LOSS && mask && scale == 0.f) {
        #pragma unroll
        for (int i = 0; i < TM; i++) {
            const int m = m0 + tr * TM + i;
            #pragma unroll
            for (int j = 0; j < TN; j++)
                C[(long long)m * ldc + n0 + tc * TN + j] = 0.f;
        }
        return;
    }

    float acc[TM][TN];
    #pragma unroll
    for (int i = 0; i < TM; i++)
        #pragma unroll
        for (int j = 0; j < TN; j++) acc[i][j] = 0.f;

    for (int k0 = 0; k0 < K; k0 += BK) {
        #pragma unroll
        for (int i = tid; i < BM * BK; i += NT) {
            int m  = i / BK;
            int kk = i % BK;
            As[kk][m] = (k0 + kk < K)
                ? A[(long long)(m0 + m) * lda + (k0 + kk)] : 0.f;
        }
        #pragma unroll
        for (int i = tid; i < BK * BN; i += NT) {
            int kk = i / BN;
            int n  = i % BN;
            Bs[kk][n] = (k0 + kk < K)
                ? Bmat[(long long)(k0 + kk) * ldb + (n0 + n)] : 0.f;
        }
        __syncthreads();

        #pragma unroll
        for (int kk = 0; kk < BK; kk++) {
            float ra[TM], rb[TN];
            #pragma unroll
            for (int i = 0; i < TM; i++) ra[i] = As[kk][tr * TM + i];
            #pragma unroll
            for (int j = 0; j < TN; j++) rb[j] = Bs[kk][tc * TN + j];
            #pragma unroll
            for (int i = 0; i < TM; i++)
                #pragma unroll
                for (int j = 0; j < TN; j++)
                    acc[i][j] = fmaf(ra[i], rb[j], acc[i][j]);
        }
        __syncthreads();
    }

    float lsum = 0.f;
    #pragma unroll
    for (int i = 0; i < TM; i++) {
        const int m = m0 + tr * TM + i;
        #pragma unroll
        for (int j = 0; j < TN; j++) {
            const int n = n0 + tc * TN + j;
            float v = acc[i][j];
            if (bias) v += bias[n];
            v *= scale;
            C[(long long)m * ldc + n] = v;
            if (LOSS) {
                float t = tgt[(long long)m * ldt + n];
                lsum += __expf(v) - t * v;
            }
        }
    }

    if (LOSS) {
        __shared__ float red[NT];
        red[tid] = lsum;
        __syncthreads();
        #pragma unroll
        for (int s = NT / 2; s > 0; s >>= 1) {
            if (tid < s) red[tid] += red[tid + s];
            __syncthreads();
        }
        if (tid == 0) atomicAdd(&g_loss_acc, (double)red[0]);
    }
}

// reg_loss = mean(|lat[b,t+1,:] - lat[b,t,:]|) over (B, T-1, RL)
__global__ void reg_kernel() {
    const long long total = (long long)B_ * (T_ - 1) * RL_;
    float local = 0.f;
    for (long long idx = blockIdx.x * (long long)blockDim.x + threadIdx.x;
         idx < total;
         idx += (long long)gridDim.x * blockDim.x) {
        int c = (int)(idx % RL_);
        long long bt = idx / RL_;
        int t = (int)(bt % (T_ - 1));
        int b = (int)(bt / (T_ - 1));
        long long base = ((long long)b * T_ + t) * RL_ + c;
        local += fabsf(g_lat[base + RL_] - g_lat[base]);
    }
    __shared__ float red[256];
    red[threadIdx.x] = local;
    __syncthreads();
    #pragma unroll
    for (int s = 128; s > 0; s >>= 1) {
        if (threadIdx.x < s) red[threadIdx.x] += red[threadIdx.x + s];
        __syncthreads();
    }
    if (threadIdx.x == 0) atomicAdd(&g_reg_acc, (double)red[0]);
}

__global__ void finalize_kernel(float* __restrict__ out) {
    out[0] = (float)(g_loss_acc / ((double)BT_ * (double)N_));
    out[1] = (float)(g_reg_acc * 0.1 / ((double)B_ * (double)(T_ - 1) * (double)RL_));
}

extern "C" void kernel_launch(void* const* d_in, const int* in_sizes, int n_in,
                              void* d_out, int out_size) {
    const float* spikes = (const float*)d_in[0];
    const int*   keep_mask = (const int*)d_in[2];
    const float* W_st  = (const float*)d_in[3];
    const float* b_st  = (const float*)d_in[4];
    const float* W_U   = (const float*)d_in[5];
    const float* b_U   = (const float*)d_in[6];
    const float* W_V   = (const float*)d_in[7];
    const float* b_V   = (const float*)d_in[8];
    const float* W_dec = (const float*)d_in[9];
    const float* b_dec = (const float*)d_in[10];

    float* out   = (float*)d_out;
    float* preds = out + 2;

    float* emb; float* h; float* lat; float* wut; float* wvt;
    cudaGetSymbolAddress((void**)&emb, g_emb);
    cudaGetSymbolAddress((void**)&h,   g_h);
    cudaGetSymbolAddress((void**)&lat, g_lat);
    cudaGetSymbolAddress((void**)&wut, g_WUt);
    cudaGetSymbolAddress((void**)&wvt, g_WVt);

    // Opt in to large dynamic SMEM for the tensor-core kernels
    const int smem_k2 = 2048 + 128 * 256 + 128 * 256;   // ~68KB
    const int smem_k3 = 2048 + 128 * 256 + 160 * 256;   // ~76KB
    cudaFuncSetAttribute(tc_gemm_k<128, RC_>,
                         cudaFuncAttributeMaxDynamicSharedMemorySize, smem_k2);
    cudaFuncSetAttribute(tc_gemm_k<160, H_>,
                         cudaFuncAttributeMaxDynamicSharedMemorySize, smem_k3);

    zero_acc_kernel<<<1, 1>>>();

    // Weight transposes (tiny)
    transpose_k<<<(RC_ * H_ + 255) / 256, 256>>>(W_U, wut, RC_, H_);
    transpose_k<<<(H_ * RL_ + 255) / 256, 256>>>(W_V, wvt, H_, RL_);

    // K1: stitch per area + bias + mask -> emb (BT, 512)
    sgemm_k<128, 32, 16, 8, 4, false><<<dim3(BT_/128, 1, R_), 128>>>(
        spikes, N_, NP_,
        W_st, NC_, (long long)NP_ * NC_,
        b_st, NC_,
        emb, RC_, NC_,
        NC_, NP_,
        keep_mask, nullptr, 0, 0);

    // K2 (tensor): h = emb @ W_U + b_U   (16384 x 256, K=512)
    tc_gemm_k<128, RC_><<<dim3(BT_/128, H_/128), 128, smem_k2>>>(
        emb, RC_, wut, b_U, h, H_);

    // K3 (tensor): lat = h @ W_V + b_V   (16384 x 320, K=256)
    tc_gemm_k<160, H_><<<dim3(BT_/128, RL_/160), 128, smem_k3>>>(
        h, H_, wvt, b_V, lat, RL_);

    // K4: decoder per area + bias -> preds, fused Poisson-NLL accumulation
    sgemm_k<128, 64, 16, 8, 4, true><<<dim3(BT_/128, 1, R_), 256>>>(
        lat, RL_, NL_,
        W_dec, NP_, (long long)NL_ * NP_,
        b_dec, NP_,
        preds, N_, NP_,
        NP_, NL_,
        nullptr, spikes, N_, NP_);

    // K5: reg loss over lat diffs
    reg_kernel<<<1024, 256>>>();

    // K6: scalars
    finalize_kernel<<<1, 1>>>(out);
}